// round 1
// baseline (speedup 1.0000x reference)
#include <cuda_runtime.h>

#define IMG 224
#define HW  (IMG * IMG)   // 50176

// Bilinear sample of a 3-channel plane-major image at (px, py), replicating the
// reference's exact semantics:
//   ind = clip(int32(nx + 224*ny), 0, HW-1)  computed from UNclipped coords,
//   w   = (1-|px-nx|)(1-|py-ny|), four terms (floor/ceil both axes),
//   integer px/py double-counts exactly like the reference.
__device__ __forceinline__ void bsample3(const float* __restrict__ im,
                                         float px, float py, float r[3])
{
    float fx = floorf(px), cx = ceilf(px);
    float fy = floorf(py), cy = ceilf(py);

    float wfx = 1.0f - (px - fx);
    float wcx = 1.0f - (cx - px);
    float wfy = 1.0f - (py - fy);
    float wcy = 1.0f - (cy - py);

    int iff = (int)(fx + 224.0f * fy);
    int icf = (int)(cx + 224.0f * fy);
    int ifc = (int)(fx + 224.0f * cy);
    int icc = (int)(cx + 224.0f * cy);
    iff = min(max(iff, 0), HW - 1);
    icf = min(max(icf, 0), HW - 1);
    ifc = min(max(ifc, 0), HW - 1);
    icc = min(max(icc, 0), HW - 1);

    float wff = wfx * wfy;
    float wcf = wcx * wfy;
    float wfc = wfx * wcy;
    float wcc = wcx * wcy;

#pragma unroll
    for (int c = 0; c < 3; c++) {
        const float* p = im + c * HW;
        float v = wff * __ldg(p + iff);
        v = fmaf(wcf, __ldg(p + icf), v);
        v = fmaf(wfc, __ldg(p + ifc), v);
        v = fmaf(wcc, __ldg(p + icc), v);
        r[c] = v;
    }
}

// Block tile: 32 (x) x 8 (y). Warp spans 32 consecutive x at fixed y so the
// transposed gather index (nx + 224*ny) is ~consecutive across lanes
// (coalesced). The stride-224 linear streams (C/M/out) still fully consume
// every 32B sector within the block (8 consecutive y per sector, one per
// ty-warp), so no sector amplification there either.
__global__ __launch_bounds__(256) void vm_kernel(
    const float* __restrict__ im1, const float* __restrict__ im2,
    const float* __restrict__ C,   const float* __restrict__ M1,
    const float* __restrict__ M2,  float* __restrict__ out)
{
    int x = blockIdx.x * 32 + threadIdx.x;   // row index of flat i (outer)
    int y = blockIdx.y * 8  + threadIdx.y;   // col index of flat i (inner)
    int n = blockIdx.z;

    int i   = x * IMG + y;                   // flat pixel index within image
    int nHW = n * HW;

    float Cx = C[(n * 2) * HW + i];
    float Cy = C[(n * 2 + 1) * HW + i];
    float m1 = M1[nHW + i];
    float m2 = M2[nHW + i];

    float fxv = (float)x;
    float fyv = (float)y;

    float a[3], b[3];
    const float* im1n = im1 + n * 3 * HW;
    const float* im2n = im2 + n * 3 * HW;

    bsample3(im1n, fxv + Cx, fyv + Cy, a);
    bsample3(im2n, fxv - Cx, fyv - Cy, b);

    float* outn = out + n * 3 * HW;
#pragma unroll
    for (int c = 0; c < 3; c++)
        outn[c * HW + i] = a[c] * m1 + b[c] * m2;
}

extern "C" void kernel_launch(void* const* d_in, const int* in_sizes, int n_in,
                              void* d_out, int out_size)
{
    const float* im1 = (const float*)d_in[0];
    const float* im2 = (const float*)d_in[1];
    const float* C   = (const float*)d_in[2];
    const float* M1  = (const float*)d_in[3];
    const float* M2  = (const float*)d_in[4];
    float* out = (float*)d_out;

    dim3 block(32, 8, 1);
    dim3 grid(IMG / 32, IMG / 8, 64);   // 7 x 28 x 64
    vm_kernel<<<grid, block>>>(im1, im2, C, M1, M2, out);
}

// round 2
// speedup vs baseline: 1.4934x; 1.4934x over previous
#include <cuda_runtime.h>

#define IMG 224
#define HW  (IMG * IMG)          // 50176
#define BX  16                   // pixels per block in x (outer dim of flat i)
#define BY  32                   // pixels per block in y (inner dim of flat i)
#define R   8                    // halo radius for C ~ N(0,1) displacements
#define TW  (BX + 2 * R + 1)     // 33  (x-extent of staged tile, contiguous)
#define TH  (BY + 2 * R + 1)     // 49  (y-extent of staged tile)
#define TILE (TW * TH)           // 1617 floats per channel plane
#define NTHREADS (BX * BY)       // 512

// Bilinear sample with exact reference semantics. Fast path reads the staged
// smem tile (valid only when all four taps are inside BOTH the tile and the
// image — then no flat-index clipping can occur and nx+224*ny == gx + 224*gy
// exactly). Fallback replicates the reference's flat-index truncate+clip
// gather from global memory (taken with probability ~1e-13 per sample).
__device__ __forceinline__ void sample3(
    const float* __restrict__ sm,   // 3 planes of TILE floats
    const float* __restrict__ gim,  // 3 planes of HW floats (global)
    float px, float py,
    int tx0, int ty0,
    float lox, float hix, float loy, float hiy,
    float r[3])
{
    float fx = floorf(px), cx = ceilf(px);
    float fy = floorf(py), cy = ceilf(py);

    float wfx = 1.0f - (px - fx);
    float wcx = 1.0f - (cx - px);
    float wfy = 1.0f - (py - fy);
    float wcy = 1.0f - (cy - py);

    float wff = wfx * wfy;
    float wcf = wcx * wfy;
    float wfc = wfx * wcy;
    float wcc = wcx * wcy;

    if (fx >= lox && cx <= hix && fy >= loy && cy <= hiy) {
        int c0 = (int)fx - tx0;
        int c1 = (int)cx - tx0;
        int r0 = (int)fy - ty0;
        int r1 = (int)cy - ty0;
        int i00 = r0 * TW + c0;
        int i01 = r0 * TW + c1;
        int i10 = r1 * TW + c0;
        int i11 = r1 * TW + c1;
#pragma unroll
        for (int ch = 0; ch < 3; ch++) {
            const float* p = sm + ch * TILE;
            float v = wff * p[i00];
            v = fmaf(wcf, p[i01], v);
            v = fmaf(wfc, p[i10], v);
            v = fmaf(wcc, p[i11], v);
            r[ch] = v;
        }
    } else {
        // Reference fallback: ind = clip(int32(nx + 224*ny), 0, HW-1)
        int iff = (int)(fx + 224.0f * fy);
        int icf = (int)(cx + 224.0f * fy);
        int ifc = (int)(fx + 224.0f * cy);
        int icc = (int)(cx + 224.0f * cy);
        iff = min(max(iff, 0), HW - 1);
        icf = min(max(icf, 0), HW - 1);
        ifc = min(max(ifc, 0), HW - 1);
        icc = min(max(icc, 0), HW - 1);
#pragma unroll
        for (int ch = 0; ch < 3; ch++) {
            const float* p = gim + ch * HW;
            float v = wff * __ldg(p + iff);
            v = fmaf(wcf, __ldg(p + icf), v);
            v = fmaf(wfc, __ldg(p + ifc), v);
            v = fmaf(wcc, __ldg(p + icc), v);
            r[ch] = v;
        }
    }
}

__global__ __launch_bounds__(NTHREADS) void vm_kernel(
    const float* __restrict__ im1, const float* __restrict__ im2,
    const float* __restrict__ C,   const float* __restrict__ M1,
    const float* __restrict__ M2,  float* __restrict__ out)
{
    __shared__ float sm[6 * TILE];   // 38808 B static

    const int X0 = blockIdx.x * BX;
    const int Y0 = blockIdx.y * BY;
    const int n  = blockIdx.z;
    const int tid = threadIdx.x;

    const int tx0 = X0 - R;
    const int ty0 = Y0 - R;

    const float* b1 = im1 + n * 3 * HW;
    const float* b2 = im2 + n * 3 * HW;

    // ── Stage the 33x49 window of all 6 channel planes into smem ──
    // smem layout: sm[ch*TILE + row*TW + col], col = x (contiguous in global),
    // row = y. Global reads are coalesced along x. Coordinates outside the
    // image are clamped; those slots are never read by the fast path.
    for (int idx = tid; idx < TILE; idx += NTHREADS) {
        int ry = idx / TW;
        int cc = idx - ry * TW;
        int gy = min(max(ty0 + ry, 0), IMG - 1);
        int gx = min(max(tx0 + cc, 0), IMG - 1);
        int g  = gy * IMG + gx;
#pragma unroll
        for (int ch = 0; ch < 3; ch++) {
            sm[ch * TILE + idx]       = __ldg(b1 + ch * HW + g);
            sm[(3 + ch) * TILE + idx] = __ldg(b2 + ch * HW + g);
        }
    }
    __syncthreads();

    // ── Per-pixel compute. Warp lanes run along y → coalesced C/M/out. ──
    const int y = Y0 + (tid & 31);
    const int x = X0 + (tid >> 5);
    const int i = x * IMG + y;
    const int nHW = n * HW;

    float Cx = C[(n * 2) * HW + i];
    float Cy = C[(n * 2 + 1) * HW + i];
    float m1 = M1[nHW + i];
    float m2 = M2[nHW + i];

    const float lox = (float)max(tx0, 0);
    const float hix = (float)min(tx0 + TW - 1, IMG - 1);
    const float loy = (float)max(ty0, 0);
    const float hiy = (float)min(ty0 + TH - 1, IMG - 1);

    float fxv = (float)x;
    float fyv = (float)y;

    float a[3], b[3];
    sample3(sm,            b1, fxv + Cx, fyv + Cy, tx0, ty0, lox, hix, loy, hiy, a);
    sample3(sm + 3 * TILE, b2, fxv - Cx, fyv - Cy, tx0, ty0, lox, hix, loy, hiy, b);

    float* outn = out + n * 3 * HW;
#pragma unroll
    for (int ch = 0; ch < 3; ch++)
        outn[ch * HW + i] = a[ch] * m1 + b[ch] * m2;
}

extern "C" void kernel_launch(void* const* d_in, const int* in_sizes, int n_in,
                              void* d_out, int out_size)
{
    const float* im1 = (const float*)d_in[0];
    const float* im2 = (const float*)d_in[1];
    const float* C   = (const float*)d_in[2];
    const float* M1  = (const float*)d_in[3];
    const float* M2  = (const float*)d_in[4];
    float* out = (float*)d_out;

    dim3 block(NTHREADS, 1, 1);
    dim3 grid(IMG / BX, IMG / BY, 64);   // 14 x 7 x 64 = 6272 blocks
    vm_kernel<<<grid, block>>>(im1, im2, C, M1, M2, out);
}

// round 3
// speedup vs baseline: 2.6375x; 1.7661x over previous
#include <cuda_runtime.h>

#define IMG 224
#define HW  (IMG * IMG)          // 50176
#define BX  16                   // output tile extent in x (outer dim of flat i)
#define BY  32                   // output tile extent in y (inner dim of flat i)
#define R   5                    // halo radius (C ~ N(0,1); fallback is exact)
#define XW  (BX + 2 * R + 1)     // 27  tile x-extent (contiguous in gather space)
#define YH  (BY + 2 * R + 1)     // 43  tile y-extent
#define TILE (XW * YH)           // 1161 elements per plane
#define NT  (BX * BY)            // 512 threads

// Exact-semantics bilinear sample. Fast path: staged smem tile (valid when all
// four taps lie inside tile ∩ image — then flat-index truncate/clip is a no-op
// and smem holds the true values). Fallback: reference's exact global gather
// with ind = clip(int32(nx + 224*ny), 0, HW-1).
__device__ __forceinline__ void sample3(
    const float2* __restrict__ sp,  // (ch0, ch1) pairs, TILE elems
    const float*  __restrict__ ss,  // ch2, TILE elems
    const float*  __restrict__ gim, // 3 planes of HW floats (global fallback)
    float px, float py,
    int tx0, int ty0,
    float lox, float hix, float loy, float hiy,
    float r[3])
{
    float fx = floorf(px), cx = ceilf(px);
    float fy = floorf(py), cy = ceilf(py);

    float wfx = 1.0f - (px - fx);
    float wcx = 1.0f - (cx - px);
    float wfy = 1.0f - (py - fy);
    float wcy = 1.0f - (cy - py);

    float wff = wfx * wfy;
    float wcf = wcx * wfy;
    float wfc = wfx * wcy;
    float wcc = wcx * wcy;

    if (fx >= lox && cx <= hix && fy >= loy && cy <= hiy) {
        int c0 = (int)fx - tx0;
        int dc = (int)cx - tx0 - c0;          // 0 or 1 (0 in the degenerate case)
        int r0 = (int)fy - ty0;
        int r1 = (int)cy - ty0;
        int t00 = r0 * XW + c0;
        int t10 = r1 * XW + c0;
        int t01 = t00 + dc;
        int t11 = t10 + dc;

        float2 pff = sp[t00];
        float2 pcf = sp[t01];
        float2 pfc = sp[t10];
        float2 pcc = sp[t11];
        float  sff = ss[t00];
        float  scf = ss[t01];
        float  sfc = ss[t10];
        float  scc = ss[t11];

        float v0 = wff * pff.x;
        v0 = fmaf(wcf, pcf.x, v0);
        v0 = fmaf(wfc, pfc.x, v0);
        v0 = fmaf(wcc, pcc.x, v0);
        float v1 = wff * pff.y;
        v1 = fmaf(wcf, pcf.y, v1);
        v1 = fmaf(wfc, pfc.y, v1);
        v1 = fmaf(wcc, pcc.y, v1);
        float v2 = wff * sff;
        v2 = fmaf(wcf, scf, v2);
        v2 = fmaf(wfc, sfc, v2);
        v2 = fmaf(wcc, scc, v2);
        r[0] = v0; r[1] = v1; r[2] = v2;
    } else {
        int iff = (int)(fx + 224.0f * fy);
        int icf = (int)(cx + 224.0f * fy);
        int ifc = (int)(fx + 224.0f * cy);
        int icc = (int)(cx + 224.0f * cy);
        iff = min(max(iff, 0), HW - 1);
        icf = min(max(icf, 0), HW - 1);
        ifc = min(max(ifc, 0), HW - 1);
        icc = min(max(icc, 0), HW - 1);
#pragma unroll
        for (int ch = 0; ch < 3; ch++) {
            const float* p = gim + ch * HW;
            float v = wff * __ldg(p + iff);
            v = fmaf(wcf, __ldg(p + icf), v);
            v = fmaf(wfc, __ldg(p + ifc), v);
            v = fmaf(wcc, __ldg(p + icc), v);
            r[ch] = v;
        }
    }
}

__global__ __launch_bounds__(NT) void vm_kernel(
    const float* __restrict__ im1, const float* __restrict__ im2,
    const float* __restrict__ C,   const float* __restrict__ M1,
    const float* __restrict__ M2,  float* __restrict__ out)
{
    __shared__ float2 sp1[TILE];   // im1 (ch0, ch1)
    __shared__ float2 sp2[TILE];   // im2 (ch0, ch1)
    __shared__ float  ss1[TILE];   // im1 ch2
    __shared__ float  ss2[TILE];   // im2 ch2

    const int X0 = blockIdx.x * BX;
    const int Y0 = blockIdx.y * BY;
    const int n  = blockIdx.z;
    const int tid = threadIdx.x;

    const int tx0 = X0 - R;        // x-origin of tile (gather contiguous dim)
    const int ty0 = Y0 - R;        // y-origin of tile

    const float* b1 = im1 + n * 3 * HW;
    const float* b2 = im2 + n * 3 * HW;

    // ── Stage the 27x43 gather window of both images (division-free loop) ──
    {
        int r = tid / XW;
        int c = tid - r * XW;
        const int DR = NT / XW;          // 18
        const int DC = NT - DR * XW;     // 26
#pragma unroll
        for (int k = tid; k < TILE; k += NT) {
            int ny = min(max(ty0 + r, 0), IMG - 1);
            int nx = min(max(tx0 + c, 0), IMG - 1);
            int g  = ny * IMG + nx;
            float a0 = __ldg(b1 + g);
            float a1 = __ldg(b1 + HW + g);
            float a2 = __ldg(b1 + 2 * HW + g);
            float d0 = __ldg(b2 + g);
            float d1 = __ldg(b2 + HW + g);
            float d2 = __ldg(b2 + 2 * HW + g);
            sp1[k] = make_float2(a0, a1);
            ss1[k] = a2;
            sp2[k] = make_float2(d0, d1);
            ss2[k] = d2;
            r += DR; c += DC;
            if (c >= XW) { c -= XW; r += 1; }
        }
    }
    __syncthreads();

    // ── Per-pixel compute; warp lanes run along y → coalesced C/M/out ──
    const int y = Y0 + (tid & 31);
    const int x = X0 + (tid >> 5);
    const int i = x * IMG + y;
    const int nHW = n * HW;

    float Cx = C[(n * 2) * HW + i];
    float Cy = C[(n * 2 + 1) * HW + i];
    float m1 = M1[nHW + i];
    float m2 = M2[nHW + i];

    const float lox = (float)max(tx0, 0);
    const float hix = (float)min(tx0 + XW - 1, IMG - 1);
    const float loy = (float)max(ty0, 0);
    const float hiy = (float)min(ty0 + YH - 1, IMG - 1);

    float fxv = (float)x;
    float fyv = (float)y;

    float a[3], b[3];
    sample3(sp1, ss1, b1, fxv + Cx, fyv + Cy, tx0, ty0, lox, hix, loy, hiy, a);
    sample3(sp2, ss2, b2, fxv - Cx, fyv - Cy, tx0, ty0, lox, hix, loy, hiy, b);

    float* outn = out + n * 3 * HW;
#pragma unroll
    for (int ch = 0; ch < 3; ch++)
        outn[ch * HW + i] = a[ch] * m1 + b[ch] * m2;
}

extern "C" void kernel_launch(void* const* d_in, const int* in_sizes, int n_in,
                              void* d_out, int out_size)
{
    const float* im1 = (const float*)d_in[0];
    const float* im2 = (const float*)d_in[1];
    const float* C   = (const float*)d_in[2];
    const float* M1  = (const float*)d_in[3];
    const float* M2  = (const float*)d_in[4];
    float* out = (float*)d_out;

    dim3 block(NT, 1, 1);
    dim3 grid(IMG / BX, IMG / BY, 64);   // 14 x 7 x 64 = 6272 blocks
    vm_kernel<<<grid, block>>>(im1, im2, C, M1, M2, out);
}